// round 13
// baseline (speedup 1.0000x reference)
#include <cuda_runtime.h>
#include <cuda_bf16.h>
#include <math.h>
#include <stdint.h>

#define BB 512
#define DD 512
#define CC 100000
#define SCALE 64.0f

#define MBT 128          // batch tile
#define NBT 128          // class tile
#define KC  64           // K chunk (128 bytes bf16)
#define NCH (DD / KC)    // 8 chunks per tile
#define NST 3            // cp.async ring stages
#define GCTA 296         // persistent CTAs (2 per SM on 148 SMs)
#define NTILES 3128      // 4 x-tiles * 782 y-tiles
#define YSTEP 74         // 296/4 tiles y-stride per CTA

// ---------------- device scratch ----------------
__device__ float          g_xn[BB * DD];          // normalized x fp32 (exact label logit)
__device__ __nv_bfloat16  g_xbf[BB * DD];         // normalized x bf16
__device__ __nv_bfloat16  g_wbf[(size_t)CC * DD]; // W * (64/||w||) bf16
__device__ float          g_wscale[CC];
__device__ float          g_expsum[BB];
__device__ float          g_nll[BB];
__device__ int            g_is64;

// ---------------- PTX helpers (baseline compute_103-safe only) --------------
__device__ __forceinline__ uint32_t smem_u32(const void* p) {
    uint32_t a;
    asm("{ .reg .u64 t; cvta.to.shared.u64 t, %1; cvt.u32.u64 %0, t; }" : "=r"(a) : "l"(p));
    return a;
}
#define CP_ASYNC16(dst, src) \
    asm volatile("cp.async.cg.shared.global [%0], [%1], 16;" :: "r"(dst), "l"(src) : "memory")
#define CP_COMMIT() asm volatile("cp.async.commit_group;" ::: "memory")
#define CP_WAIT(n)  asm volatile("cp.async.wait_group %0;" :: "n"(n) : "memory")

#define LDSM4(r, addr) \
    asm volatile("ldmatrix.sync.aligned.m8n8.x4.shared.b16 {%0,%1,%2,%3}, [%4];" \
        : "=r"((r)[0]), "=r"((r)[1]), "=r"((r)[2]), "=r"((r)[3]) : "r"(addr))

#define MMA16816(d, a, b0v, b1v) \
    asm volatile("mma.sync.aligned.m16n8k16.row.col.f32.bf16.bf16.f32 " \
        "{%0,%1,%2,%3}, {%4,%5,%6,%7}, {%8,%9}, {%0,%1,%2,%3};" \
        : "+f"((d)[0]), "+f"((d)[1]), "+f"((d)[2]), "+f"((d)[3]) \
        : "r"((a)[0]), "r"((a)[1]), "r"((a)[2]), "r"((a)[3]), "r"(b0v), "r"(b1v))

// ---------------- fused prep: W norm+convert | x norm | label probe ---------
// bid <  12500 : W rows (8 per block, one warp per row)
// 12500..12563 : x rows (8 per block, one warp per row) + expsum zero
// bid == 12564 : label dtype probe
__global__ void k_prep(const float* __restrict__ x, const float* __restrict__ w,
                       const int* __restrict__ lab) {
    const int bid = blockIdx.x;
    const int warp = threadIdx.x >> 5;
    const int lane = threadIdx.x & 31;

    if (bid < 12500) {                         // ---- W path ----
        const int c = bid * 8 + warp;
        const float4* w4 = (const float4*)(w + (size_t)c * DD);
        float4 v[4];
        float ss = 0.0f;
        #pragma unroll
        for (int q = 0; q < 4; q++) {
            v[q] = w4[q * 32 + lane];
            ss += v[q].x * v[q].x + v[q].y * v[q].y + v[q].z * v[q].z + v[q].w * v[q].w;
        }
        #pragma unroll
        for (int o = 16; o > 0; o >>= 1) ss += __shfl_xor_sync(0xffffffffu, ss, o);
        const float sc = SCALE / fmaxf(sqrtf(ss), 1e-12f);
        if (lane == 0) g_wscale[c] = sc;
        __nv_bfloat16* dst = g_wbf + (size_t)c * DD;
        #pragma unroll
        for (int q = 0; q < 4; q++) {
            __nv_bfloat162 h0 = __floats2bfloat162_rn(v[q].x * sc, v[q].y * sc);
            __nv_bfloat162 h1 = __floats2bfloat162_rn(v[q].z * sc, v[q].w * sc);
            uint2 u;
            u.x = *(uint32_t*)&h0; u.y = *(uint32_t*)&h1;
            *(uint2*)(dst + q * 128 + lane * 4) = u;
        }
    } else if (bid < 12564) {                  // ---- x path ----
        const int m = (bid - 12500) * 8 + warp;
        const float4* x4 = (const float4*)(x + (size_t)m * DD);
        float4 v[4];
        float ss = 0.0f;
        #pragma unroll
        for (int q = 0; q < 4; q++) {
            v[q] = x4[q * 32 + lane];
            ss += v[q].x * v[q].x + v[q].y * v[q].y + v[q].z * v[q].z + v[q].w * v[q].w;
        }
        #pragma unroll
        for (int o = 16; o > 0; o >>= 1) ss += __shfl_xor_sync(0xffffffffu, ss, o);
        const float inv = 1.0f / fmaxf(sqrtf(ss), 1e-12f);
        if (lane == 0) g_expsum[m] = 0.0f;     // re-zeroed every graph replay
        float4* xo = (float4*)(g_xn + (size_t)m * DD);
        __nv_bfloat16* xb = g_xbf + (size_t)m * DD;
        #pragma unroll
        for (int q = 0; q < 4; q++) {
            float4 o4 = make_float4(v[q].x * inv, v[q].y * inv, v[q].z * inv, v[q].w * inv);
            xo[q * 32 + lane] = o4;
            __nv_bfloat162 h0 = __floats2bfloat162_rn(o4.x, o4.y);
            __nv_bfloat162 h1 = __floats2bfloat162_rn(o4.z, o4.w);
            uint2 u;
            u.x = *(uint32_t*)&h0; u.y = *(uint32_t*)&h1;
            *(uint2*)(xb + q * 128 + lane * 4) = u;
        }
    } else {                                   // ---- label probe ----
        __shared__ int s_any;
        if (threadIdx.x == 0) s_any = 0;
        __syncthreads();
        if (lab[2 * threadIdx.x + 1] != 0) atomicOr(&s_any, 1);
        __syncthreads();
        if (threadIdx.x == 0) g_is64 = (s_any == 0) ? 1 : 0;
    }
}

// ---------------- persistent bf16 mma.sync GEMM + fused exp/sum -------------
// 296 resident CTAs (2/SM), each owns batch tile x=cta&3 and walks y tiles
// y0 + i*74. cp.async ring (3 stages) rolls ACROSS tile boundaries so the
// next tile's loads overlap this tile's epilogue.
#define SMEM_BYTES (NST * 32768)   // 3 stages x (A 16KB + B 16KB)

__global__ __launch_bounds__(256, 2) void k_gemm() {
    extern __shared__ char smem[];
    __shared__ float red[MBT];
    const uint32_t sA = smem_u32(smem);          // stage s: A at s*16384
    const uint32_t sB = sA + NST * 16384;        // stage s: B at s*16384

    const int tid  = threadIdx.x;
    const int lane = tid & 31;
    const int wid  = tid >> 5;
    const int wm   = wid >> 2;                   // 0..1
    const int wn   = wid & 3;                    // 0..3

    const int cta   = blockIdx.x;                // 0..295
    const int mBase = (cta & 3) * MBT;           // fixed batch tile
    const int y0    = cta >> 2;                  // first y tile
    const int ntiles = (cta < NTILES - 10 * GCTA) ? 11 : 10;   // 168 CTAs get 11
    const int G = ntiles * NCH;                  // total chunks this CTA

    // ---- staging addressing: 1024 16B segs per operand per chunk ----
    const int srow = tid >> 3;                   // 0..31
    const int scol = tid & 7;
    const uint32_t st0 = (uint32_t)(srow * 128 + ((scol ^ (srow & 7)) << 4));
    const uint32_t st_a0 = sA + st0;
    const uint32_t st_b0 = sB + st0;
    const __nv_bfloat16* gp_a0 = g_xbf + (size_t)(mBase + srow) * DD + scol * 8;

    auto stage = [&](int g, int buf) {
        const int i  = g >> 3;
        const int kc = g & 7;
        const int cB0 = (y0 + i * YSTEP) * NBT;
        const uint32_t bo = (uint32_t)(buf * 16384);
        const __nv_bfloat16* ga = gp_a0 + kc * KC;
        #pragma unroll
        for (int s = 0; s < 4; s++) {
            int br = cB0 + srow + s * 32;
            br = min(br, CC - 1);                // clamp; masked in epilogue
            CP_ASYNC16(st_a0 + bo + s * 4096, ga + s * 32 * DD);
            CP_ASYNC16(st_b0 + bo + s * 4096,
                       g_wbf + (size_t)br * DD + kc * KC + scol * 8);
        }
        CP_COMMIT();
    };

    // ---- ldmatrix per-lane addressing (validated R8) ----
    const int arow = (lane & 7) + 8 * ((lane >> 3) & 1);
    const int akh  = lane >> 4;
    const int brow = (lane & 7) + 8 * (lane >> 4);
    const int bkh  = (lane >> 3) & 1;
    const int swz  = lane & 7;
    uint32_t aptr[4], bptr[2];
    #pragma unroll
    for (int mi = 0; mi < 4; mi++)
        aptr[mi] = sA + (uint32_t)((wm * 64 + mi * 16 + arow) * 128);
    #pragma unroll
    for (int jp = 0; jp < 2; jp++)
        bptr[jp] = sB + (uint32_t)((wn * 32 + jp * 16 + brow) * 128);

    // ---- prologue: chunks 0,1 in flight ----
    stage(0, 0);
    stage(1, 1);
    int gstage = 2, bufs = 2, bufc = 0;

    float d[4][4][4];
    const int q  = lane & 3;
    const int g4 = lane >> 2;

    for (int i = 0; i < ntiles; i++) {
        #pragma unroll
        for (int mi = 0; mi < 4; mi++)
            #pragma unroll
            for (int nj = 0; nj < 4; nj++)
                #pragma unroll
                for (int r = 0; r < 4; r++) d[mi][nj][r] = 0.0f;

        for (int kc = 0; kc < NCH; kc++) {
            const int g = i * NCH + kc;
            if (g + 1 < G) CP_WAIT(1); else CP_WAIT(0);
            __syncthreads();                     // chunk g landed; ring buf free
            if (gstage < G) {
                stage(gstage, bufs);
                gstage++;
                if (++bufs == NST) bufs = 0;
            }

            const uint32_t bufoff = (uint32_t)(bufc * 16384);
            #pragma unroll
            for (int ks = 0; ks < 4; ks++) {
                const uint32_t cA = (uint32_t)(((ks * 2 + akh) ^ swz) << 4);
                const uint32_t cB = (uint32_t)(((ks * 2 + bkh) ^ swz) << 4);
                uint32_t a[4][4], b[2][4];
                #pragma unroll
                for (int mi = 0; mi < 4; mi++) LDSM4(a[mi], aptr[mi] + bufoff + cA);
                #pragma unroll
                for (int jp = 0; jp < 2; jp++) LDSM4(b[jp], bptr[jp] + bufoff + cB);
                #pragma unroll
                for (int mi = 0; mi < 4; mi++) {
                    MMA16816(d[mi][0], a[mi], b[0][0], b[0][1]);
                    MMA16816(d[mi][1], a[mi], b[0][2], b[0][3]);
                    MMA16816(d[mi][2], a[mi], b[1][0], b[1][1]);
                    MMA16816(d[mi][3], a[mi], b[1][2], b[1][3]);
                }
            }
            if (++bufc == NST) bufc = 0;
        }

        // ---- epilogue tile i (next tile's loads already in flight) ----
        const int cBase = (y0 + i * YSTEP) * NBT;
        if (tid < MBT) red[tid] = 0.0f;
        __syncthreads();
        #pragma unroll
        for (int mi = 0; mi < 4; mi++) {
            float r0 = 0.0f, r1 = 0.0f;
            #pragma unroll
            for (int nj = 0; nj < 4; nj++) {
                int c0 = cBase + wn * 32 + nj * 8 + q * 2;
                if (c0 < CC)     { r0 += __expf(d[mi][nj][0] - SCALE);
                                   r1 += __expf(d[mi][nj][2] - SCALE); }
                if (c0 + 1 < CC) { r0 += __expf(d[mi][nj][1] - SCALE);
                                   r1 += __expf(d[mi][nj][3] - SCALE); }
            }
            r0 += __shfl_xor_sync(0xffffffffu, r0, 1);
            r0 += __shfl_xor_sync(0xffffffffu, r0, 2);
            r1 += __shfl_xor_sync(0xffffffffu, r1, 1);
            r1 += __shfl_xor_sync(0xffffffffu, r1, 2);
            if (q == 0) {
                atomicAdd(&red[wm * 64 + mi * 16 + g4],     r0);
                atomicAdd(&red[wm * 64 + mi * 16 + 8 + g4], r1);
            }
        }
        __syncthreads();
        if (tid < MBT) atomicAdd(&g_expsum[mBase + tid], red[tid]);
    }
}

// ---------------- per-row nll (exact fp32 label logit) ----------------------
__global__ void k_nll(const float* __restrict__ w, const void* __restrict__ labv) {
    const int warp = threadIdx.x >> 5;
    const int lane = threadIdx.x & 31;
    const int i = blockIdx.x * 8 + warp;
    long long yi;
    if (g_is64) yi = ((const long long*)labv)[i];
    else        yi = (long long)((const int*)labv)[i];
    const float4* a4 = (const float4*)(g_xn + i * DD);
    const float4* w4 = (const float4*)(w + (size_t)yi * DD);
    float dot = 0.0f;
    #pragma unroll
    for (int qq = 0; qq < 4; qq++) {
        float4 a = a4[qq * 32 + lane];
        float4 b = w4[qq * 32 + lane];
        dot += a.x * b.x + a.y * b.y + a.z * b.z + a.w * b.w;
    }
    #pragma unroll
    for (int o = 16; o > 0; o >>= 1) dot += __shfl_xor_sync(0xffffffffu, dot, o);
    if (lane == 0)
        g_nll[i] = SCALE + logf(g_expsum[i]) - g_wscale[yi] * dot;
}

// ---------------- deterministic final reduce --------------------------------
__global__ void k_reduce(float* __restrict__ out) {
    __shared__ float sm[16];
    const int t = threadIdx.x;
    float v = g_nll[t];
    #pragma unroll
    for (int o = 16; o > 0; o >>= 1) v += __shfl_xor_sync(0xffffffffu, v, o);
    if ((t & 31) == 0) sm[t >> 5] = v;
    __syncthreads();
    if (t < 16) {
        float u = sm[t];
        #pragma unroll
        for (int o = 8; o > 0; o >>= 1) u += __shfl_xor_sync(0x0000ffffu, u, o);
        if (t == 0) out[0] = u * (1.0f / (float)BB);
    }
}

// ---------------- launch -----------------------------------------------------
extern "C" void kernel_launch(void* const* d_in, const int* in_sizes, int n_in,
                              void* d_out, int out_size) {
    (void)out_size;
    const float* x = nullptr;
    const float* w = nullptr;
    const void* lab = nullptr;
    for (int i = 0; i < n_in; i++) {
        if (in_sizes[i] == BB * DD)      x = (const float*)d_in[i];
        else if (in_sizes[i] == CC * DD) w = (const float*)d_in[i];
        else if (in_sizes[i] == BB)      lab = d_in[i];
    }

    cudaFuncSetAttribute(k_gemm, cudaFuncAttributeMaxDynamicSharedMemorySize, SMEM_BYTES);

    k_prep<<<12565, 256>>>(x, w, (const int*)lab);
    k_gemm<<<GCTA, 256, SMEM_BYTES>>>();
    k_nll<<<BB / 8, 256>>>(w, lab);
    k_reduce<<<1, BB>>>((float*)d_out);
}

// round 14
// speedup vs baseline: 1.0810x; 1.0810x over previous
#include <cuda_runtime.h>
#include <cuda_bf16.h>
#include <math.h>
#include <stdint.h>

#define BB 512
#define DD 512
#define CC 100000
#define SCALE 64.0f

#define MBT 128          // batch tile
#define NBT 128          // class tile
#define KC  64           // K chunk (128 bytes bf16)
#define NCH (DD / KC)    // 8 chunks
#define NST 3            // cp.async pipeline stages

// ---------------- device scratch ----------------
__device__ float          g_xn[BB * DD];          // normalized x fp32 (exact label logit)
__device__ __nv_bfloat16  g_xbf[BB * DD];         // normalized x bf16
__device__ __nv_bfloat16  g_wbf[(size_t)CC * DD]; // W * (64/||w||) bf16
__device__ float          g_wscale[CC];
__device__ float          g_expsum[BB];
__device__ float          g_nll[BB];
__device__ int            g_is64;
__device__ int            g_ctr;                  // last-block ticket (reset each replay)

// ---------------- PTX helpers (baseline compute_103-safe only) --------------
__device__ __forceinline__ uint32_t smem_u32(const void* p) {
    uint32_t a;
    asm("{ .reg .u64 t; cvta.to.shared.u64 t, %1; cvt.u32.u64 %0, t; }" : "=r"(a) : "l"(p));
    return a;
}
#define CP_ASYNC16(dst, src) \
    asm volatile("cp.async.cg.shared.global [%0], [%1], 16;" :: "r"(dst), "l"(src) : "memory")
#define CP_COMMIT() asm volatile("cp.async.commit_group;" ::: "memory")
#define CP_WAIT(n)  asm volatile("cp.async.wait_group %0;" :: "n"(n) : "memory")

#define LDSM4(r, addr) \
    asm volatile("ldmatrix.sync.aligned.m8n8.x4.shared.b16 {%0,%1,%2,%3}, [%4];" \
        : "=r"((r)[0]), "=r"((r)[1]), "=r"((r)[2]), "=r"((r)[3]) : "r"(addr))

#define MMA16816(d, a, b0v, b1v) \
    asm volatile("mma.sync.aligned.m16n8k16.row.col.f32.bf16.bf16.f32 " \
        "{%0,%1,%2,%3}, {%4,%5,%6,%7}, {%8,%9}, {%0,%1,%2,%3};" \
        : "+f"((d)[0]), "+f"((d)[1]), "+f"((d)[2]), "+f"((d)[3]) \
        : "r"((a)[0]), "r"((a)[1]), "r"((a)[2]), "r"((a)[3]), "r"(b0v), "r"(b1v))

// ---------------- fused prep: W norm+convert | x norm | label probe ---------
// bid <  12500 : W rows (8 per block, one warp per row)
// 12500..12563 : x rows (8 per block, one warp per row) + expsum zero
// bid == 12564 : label dtype probe
__global__ void k_prep(const float* __restrict__ x, const float* __restrict__ w,
                       const int* __restrict__ lab) {
    const int bid = blockIdx.x;
    const int warp = threadIdx.x >> 5;
    const int lane = threadIdx.x & 31;

    if (bid < 12500) {                         // ---- W path ----
        const int c = bid * 8 + warp;
        const float4* w4 = (const float4*)(w + (size_t)c * DD);
        float4 v[4];
        float ss = 0.0f;
        #pragma unroll
        for (int q = 0; q < 4; q++) {
            v[q] = w4[q * 32 + lane];
            ss += v[q].x * v[q].x + v[q].y * v[q].y + v[q].z * v[q].z + v[q].w * v[q].w;
        }
        #pragma unroll
        for (int o = 16; o > 0; o >>= 1) ss += __shfl_xor_sync(0xffffffffu, ss, o);
        const float sc = SCALE / fmaxf(sqrtf(ss), 1e-12f);
        if (lane == 0) g_wscale[c] = sc;
        __nv_bfloat16* dst = g_wbf + (size_t)c * DD;
        #pragma unroll
        for (int q = 0; q < 4; q++) {
            __nv_bfloat162 h0 = __floats2bfloat162_rn(v[q].x * sc, v[q].y * sc);
            __nv_bfloat162 h1 = __floats2bfloat162_rn(v[q].z * sc, v[q].w * sc);
            uint2 u;
            u.x = *(uint32_t*)&h0; u.y = *(uint32_t*)&h1;
            *(uint2*)(dst + q * 128 + lane * 4) = u;
        }
    } else if (bid < 12564) {                  // ---- x path ----
        const int m = (bid - 12500) * 8 + warp;
        const float4* x4 = (const float4*)(x + (size_t)m * DD);
        float4 v[4];
        float ss = 0.0f;
        #pragma unroll
        for (int q = 0; q < 4; q++) {
            v[q] = x4[q * 32 + lane];
            ss += v[q].x * v[q].x + v[q].y * v[q].y + v[q].z * v[q].z + v[q].w * v[q].w;
        }
        #pragma unroll
        for (int o = 16; o > 0; o >>= 1) ss += __shfl_xor_sync(0xffffffffu, ss, o);
        const float inv = 1.0f / fmaxf(sqrtf(ss), 1e-12f);
        if (lane == 0) g_expsum[m] = 0.0f;     // re-zeroed every graph replay
        float4* xo = (float4*)(g_xn + (size_t)m * DD);
        __nv_bfloat16* xb = g_xbf + (size_t)m * DD;
        #pragma unroll
        for (int q = 0; q < 4; q++) {
            float4 o4 = make_float4(v[q].x * inv, v[q].y * inv, v[q].z * inv, v[q].w * inv);
            xo[q * 32 + lane] = o4;
            __nv_bfloat162 h0 = __floats2bfloat162_rn(o4.x, o4.y);
            __nv_bfloat162 h1 = __floats2bfloat162_rn(o4.z, o4.w);
            uint2 u;
            u.x = *(uint32_t*)&h0; u.y = *(uint32_t*)&h1;
            *(uint2*)(xb + q * 128 + lane * 4) = u;
        }
    } else {                                   // ---- label probe ----
        __shared__ int s_any;
        if (threadIdx.x == 0) s_any = 0;
        __syncthreads();
        if (lab[2 * threadIdx.x + 1] != 0) atomicOr(&s_any, 1);
        __syncthreads();
        if (threadIdx.x == 0) g_is64 = (s_any == 0) ? 1 : 0;
    }
}

// ---------------- bf16 mma.sync GEMM + fused exp/sum epilogue ---------------
// R12 config verbatim (best measured): tile 128x128, K=512, 3-stage cp.async
// ring, ONE __syncthreads per chunk, 2 CTAs/SM via __launch_bounds__(256,2).
// 8 warps (2 m x 4 n), warp tile 64x32, m16n8k16 via ldmatrix.
#define SMEM_BYTES (NST * 32768)   // 98304: 3 stages x (A 16KB + B 16KB)

__global__ __launch_bounds__(256, 2) void k_gemm() {
    extern __shared__ char smem[];
    __shared__ float red[MBT];
    const uint32_t sA = smem_u32(smem);          // stage s: A at s*16384
    const uint32_t sB = sA + NST * 16384;        // stage s: B at s*16384

    const int tid  = threadIdx.x;
    const int lane = tid & 31;
    const int wid  = tid >> 5;
    const int wm   = wid >> 2;                   // 0..1
    const int wn   = wid & 3;                    // 0..3
    const int mBase = blockIdx.x * MBT;
    const int cBase = blockIdx.y * NBT;

    // ---- staging precompute: 1024 16B segs per operand per chunk ----
    const int srow = tid >> 3;                   // 0..31
    const int scol = tid & 7;
    const uint32_t st0 = (uint32_t)(srow * 128 + ((scol ^ (srow & 7)) << 4));
    const uint32_t st_a0 = sA + st0;
    const uint32_t st_b0 = sB + st0;
    const __nv_bfloat16* gp_a0 = g_xbf + (size_t)(mBase + srow) * DD + scol * 8;
    const __nv_bfloat16* gp_b[4];
    #pragma unroll
    for (int s = 0; s < 4; s++) {
        int br = cBase + srow + s * 32; if (br >= CC) br = CC - 1; // clamp; masked later
        gp_b[s] = g_wbf + (size_t)br * DD + scol * 8;
    }

    // ---- ldmatrix per-lane addressing (validated in R8) ----
    const int arow = (lane & 7) + 8 * ((lane >> 3) & 1);
    const int akh  = lane >> 4;
    const int brow = (lane & 7) + 8 * (lane >> 4);
    const int bkh  = (lane >> 3) & 1;
    const int swz  = lane & 7;
    uint32_t aptr[4], bptr[2];
    #pragma unroll
    for (int mi = 0; mi < 4; mi++)
        aptr[mi] = sA + (uint32_t)((wm * 64 + mi * 16 + arow) * 128);
    #pragma unroll
    for (int jp = 0; jp < 2; jp++)
        bptr[jp] = sB + (uint32_t)((wn * 32 + jp * 16 + brow) * 128);

    float d[4][4][4];
    #pragma unroll
    for (int mi = 0; mi < 4; mi++)
        #pragma unroll
        for (int nj = 0; nj < 4; nj++)
            #pragma unroll
            for (int r = 0; r < 4; r++) d[mi][nj][r] = 0.0f;

    // ---- prologue: stage chunks 0,1 into bufs 0,1 ----
    #pragma unroll
    for (int p = 0; p < 2; p++) {
        const uint32_t bo = (uint32_t)(p * 16384);
        #pragma unroll
        for (int s = 0; s < 4; s++) {
            CP_ASYNC16(st_a0 + bo + s * 4096, gp_a0 + s * 32 * DD + p * KC);
            CP_ASYNC16(st_b0 + bo + s * 4096, gp_b[s] + p * KC);
        }
        CP_COMMIT();
    }

    int bufc = 0;                                // kc % 3
    for (int kc = 0; kc < NCH; kc++) {
        if (kc + 1 < NCH) CP_WAIT(1); else CP_WAIT(0);
        __syncthreads();                         // chunk kc landed; buf (kc-1)%3 free
        if (kc + 2 < NCH) {
            int bufn = bufc - 1; if (bufn < 0) bufn += NST;   // (kc+2) % 3
            const uint32_t nb = (uint32_t)(bufn * 16384);
            #pragma unroll
            for (int s = 0; s < 4; s++) {
                CP_ASYNC16(st_a0 + nb + s * 4096, gp_a0 + s * 32 * DD + (kc + 2) * KC);
                CP_ASYNC16(st_b0 + nb + s * 4096, gp_b[s] + (kc + 2) * KC);
            }
            CP_COMMIT();
        }

        const uint32_t bufoff = (uint32_t)(bufc * 16384);
        #pragma unroll
        for (int ks = 0; ks < 4; ks++) {
            const uint32_t cA = (uint32_t)(((ks * 2 + akh) ^ swz) << 4);
            const uint32_t cB = (uint32_t)(((ks * 2 + bkh) ^ swz) << 4);
            uint32_t a[4][4], b[2][4];
            #pragma unroll
            for (int mi = 0; mi < 4; mi++) LDSM4(a[mi], aptr[mi] + bufoff + cA);
            #pragma unroll
            for (int jp = 0; jp < 2; jp++) LDSM4(b[jp], bptr[jp] + bufoff + cB);
            #pragma unroll
            for (int mi = 0; mi < 4; mi++) {
                MMA16816(d[mi][0], a[mi], b[0][0], b[0][1]);
                MMA16816(d[mi][1], a[mi], b[0][2], b[0][3]);
                MMA16816(d[mi][2], a[mi], b[1][0], b[1][1]);
                MMA16816(d[mi][3], a[mi], b[1][2], b[1][3]);
            }
        }
        if (++bufc == NST) bufc = 0;
    }

    // ---- epilogue: logits are d[] directly (scale folded into g_wbf) ----
    if (tid < MBT) red[tid] = 0.0f;
    __syncthreads();

    const int q  = lane & 3;
    const int g4 = lane >> 2;
    #pragma unroll
    for (int mi = 0; mi < 4; mi++) {
        float r0 = 0.0f, r1 = 0.0f;
        #pragma unroll
        for (int nj = 0; nj < 4; nj++) {
            int c0 = cBase + wn * 32 + nj * 8 + q * 2;
            if (c0 < CC)     { r0 += __expf(d[mi][nj][0] - SCALE);
                               r1 += __expf(d[mi][nj][2] - SCALE); }
            if (c0 + 1 < CC) { r0 += __expf(d[mi][nj][1] - SCALE);
                               r1 += __expf(d[mi][nj][3] - SCALE); }
        }
        r0 += __shfl_xor_sync(0xffffffffu, r0, 1);
        r0 += __shfl_xor_sync(0xffffffffu, r0, 2);
        r1 += __shfl_xor_sync(0xffffffffu, r1, 1);
        r1 += __shfl_xor_sync(0xffffffffu, r1, 2);
        if (q == 0) {
            atomicAdd(&red[wm * 64 + mi * 16 + g4],     r0);
            atomicAdd(&red[wm * 64 + mi * 16 + 8 + g4], r1);
        }
    }
    __syncthreads();
    if (tid < MBT) atomicAdd(&g_expsum[mBase + tid], red[tid]);
}

// ---------------- fused nll + final reduce (last-block pattern) -------------
// 64 blocks x 8 warps: warp computes one row's exact fp32 label logit + nll.
// Last block to finish does the deterministic fixed-order reduce of g_nll
// and resets the ticket counter for the next graph replay.
__global__ void k_nll(const float* __restrict__ w, const void* __restrict__ labv,
                      float* __restrict__ out) {
    __shared__ bool s_last;
    __shared__ float sm[8];
    const int warp = threadIdx.x >> 5;
    const int lane = threadIdx.x & 31;
    const int i = blockIdx.x * 8 + warp;
    long long yi;
    if (g_is64) yi = ((const long long*)labv)[i];
    else        yi = (long long)((const int*)labv)[i];
    const float4* a4 = (const float4*)(g_xn + i * DD);
    const float4* w4 = (const float4*)(w + (size_t)yi * DD);
    float dot = 0.0f;
    #pragma unroll
    for (int qq = 0; qq < 4; qq++) {
        float4 a = a4[qq * 32 + lane];
        float4 b = w4[qq * 32 + lane];
        dot += a.x * b.x + a.y * b.y + a.z * b.z + a.w * b.w;
    }
    #pragma unroll
    for (int o = 16; o > 0; o >>= 1) dot += __shfl_xor_sync(0xffffffffu, dot, o);
    if (lane == 0) {
        g_nll[i] = SCALE + logf(g_expsum[i]) - g_wscale[yi] * dot;
        __threadfence();                         // publish before ticket
    }
    __syncthreads();
    if (threadIdx.x == 0) {
        int t = atomicAdd(&g_ctr, 1);
        s_last = (t == 63);                      // 64 blocks total
    }
    __syncthreads();
    if (s_last) {
        __threadfence();                         // acquire all g_nll writes
        float v = g_nll[threadIdx.x] + g_nll[threadIdx.x + 256];
        #pragma unroll
        for (int o = 16; o > 0; o >>= 1) v += __shfl_xor_sync(0xffffffffu, v, o);
        if (lane == 0) sm[warp] = v;
        __syncthreads();
        if (threadIdx.x < 8) {
            float u = sm[threadIdx.x];
            #pragma unroll
            for (int o = 4; o > 0; o >>= 1) u += __shfl_xor_sync(0x000000ffu, u, o);
            if (threadIdx.x == 0) {
                out[0] = u * (1.0f / (float)BB);
                g_ctr = 0;                       // reset for next replay
            }
        }
    }
}

// ---------------- launch -----------------------------------------------------
extern "C" void kernel_launch(void* const* d_in, const int* in_sizes, int n_in,
                              void* d_out, int out_size) {
    (void)out_size;
    const float* x = nullptr;
    const float* w = nullptr;
    const void* lab = nullptr;
    for (int i = 0; i < n_in; i++) {
        if (in_sizes[i] == BB * DD)      x = (const float*)d_in[i];
        else if (in_sizes[i] == CC * DD) w = (const float*)d_in[i];
        else if (in_sizes[i] == BB)      lab = d_in[i];
    }

    cudaFuncSetAttribute(k_gemm, cudaFuncAttributeMaxDynamicSharedMemorySize, SMEM_BYTES);

    k_prep<<<12565, 256>>>(x, w, (const int*)lab);
    dim3 g3(BB / MBT, (CC + NBT - 1) / NBT);   // (4, 782): batch-fast for L2 W reuse
    k_gemm<<<g3, 256, SMEM_BYTES>>>();
    k_nll<<<BB / 8, 256>>>(w, lab, (float*)d_out);
}

// round 16
// speedup vs baseline: 1.2385x; 1.1457x over previous
#include <cuda_runtime.h>
#include <cuda_bf16.h>
#include <math.h>
#include <stdint.h>

#define BB 512
#define DD 512
#define CC 100000
#define SCALE 64.0f

#define MBT 128          // batch tile
#define NBT 128          // class tile
#define KC  64           // K chunk (128 bytes bf16)
#define NCH (DD / KC)    // 8 chunks
#define NST 3            // cp.async pipeline stages

// ---------------- device scratch ----------------
__device__ float          g_xn[BB * DD];          // normalized x fp32 (exact label logit)
__device__ __nv_bfloat16  g_xbf[BB * DD];         // normalized x bf16
__device__ __nv_bfloat16  g_wbf[(size_t)CC * DD]; // W * (64/||w||) bf16
__device__ float          g_wscale[CC];
__device__ float          g_expsum[BB];
__device__ float          g_nll[BB];
__device__ int            g_is64;
__device__ int            g_ctr;                  // last-block ticket (reset each replay)

// ---------------- PTX helpers (baseline compute_103-safe only) --------------
__device__ __forceinline__ uint32_t smem_u32(const void* p) {
    uint32_t a;
    asm("{ .reg .u64 t; cvta.to.shared.u64 t, %1; cvt.u32.u64 %0, t; }" : "=r"(a) : "l"(p));
    return a;
}
#define CP_ASYNC16(dst, src) \
    asm volatile("cp.async.cg.shared.global [%0], [%1], 16;" :: "r"(dst), "l"(src) : "memory")
#define CP_COMMIT() asm volatile("cp.async.commit_group;" ::: "memory")
#define CP_WAIT(n)  asm volatile("cp.async.wait_group %0;" :: "n"(n) : "memory")

#define LDSM4(r, addr) \
    asm volatile("ldmatrix.sync.aligned.m8n8.x4.shared.b16 {%0,%1,%2,%3}, [%4];" \
        : "=r"((r)[0]), "=r"((r)[1]), "=r"((r)[2]), "=r"((r)[3]) : "r"(addr))

#define MMA16816(d, a, b0v, b1v) \
    asm volatile("mma.sync.aligned.m16n8k16.row.col.f32.bf16.bf16.f32 " \
        "{%0,%1,%2,%3}, {%4,%5,%6,%7}, {%8,%9}, {%0,%1,%2,%3};" \
        : "+f"((d)[0]), "+f"((d)[1]), "+f"((d)[2]), "+f"((d)[3]) \
        : "r"((a)[0]), "r"((a)[1]), "r"((a)[2]), "r"((a)[3]), "r"(b0v), "r"(b1v))

// ---------------- fused prep: W norm+convert | x norm | label probe ---------
__global__ void k_prep(const float* __restrict__ x, const float* __restrict__ w,
                       const int* __restrict__ lab) {
    const int bid = blockIdx.x;
    const int warp = threadIdx.x >> 5;
    const int lane = threadIdx.x & 31;

    if (bid < 12500) {                         // ---- W path ----
        const int c = bid * 8 + warp;
        const float4* w4 = (const float4*)(w + (size_t)c * DD);
        float4 v[4];
        float ss = 0.0f;
        #pragma unroll
        for (int q = 0; q < 4; q++) {
            v[q] = w4[q * 32 + lane];
            ss += v[q].x * v[q].x + v[q].y * v[q].y + v[q].z * v[q].z + v[q].w * v[q].w;
        }
        #pragma unroll
        for (int o = 16; o > 0; o >>= 1) ss += __shfl_xor_sync(0xffffffffu, ss, o);
        const float sc = SCALE / fmaxf(sqrtf(ss), 1e-12f);
        if (lane == 0) g_wscale[c] = sc;
        __nv_bfloat16* dst = g_wbf + (size_t)c * DD;
        #pragma unroll
        for (int q = 0; q < 4; q++) {
            __nv_bfloat162 h0 = __floats2bfloat162_rn(v[q].x * sc, v[q].y * sc);
            __nv_bfloat162 h1 = __floats2bfloat162_rn(v[q].z * sc, v[q].w * sc);
            uint2 u;
            u.x = *(uint32_t*)&h0; u.y = *(uint32_t*)&h1;
            *(uint2*)(dst + q * 128 + lane * 4) = u;
        }
    } else if (bid < 12564) {                  // ---- x path ----
        const int m = (bid - 12500) * 8 + warp;
        const float4* x4 = (const float4*)(x + (size_t)m * DD);
        float4 v[4];
        float ss = 0.0f;
        #pragma unroll
        for (int q = 0; q < 4; q++) {
            v[q] = x4[q * 32 + lane];
            ss += v[q].x * v[q].x + v[q].y * v[q].y + v[q].z * v[q].z + v[q].w * v[q].w;
        }
        #pragma unroll
        for (int o = 16; o > 0; o >>= 1) ss += __shfl_xor_sync(0xffffffffu, ss, o);
        const float inv = 1.0f / fmaxf(sqrtf(ss), 1e-12f);
        if (lane == 0) g_expsum[m] = 0.0f;     // re-zeroed every graph replay
        float4* xo = (float4*)(g_xn + (size_t)m * DD);
        __nv_bfloat16* xb = g_xbf + (size_t)m * DD;
        #pragma unroll
        for (int q = 0; q < 4; q++) {
            float4 o4 = make_float4(v[q].x * inv, v[q].y * inv, v[q].z * inv, v[q].w * inv);
            xo[q * 32 + lane] = o4;
            __nv_bfloat162 h0 = __floats2bfloat162_rn(o4.x, o4.y);
            __nv_bfloat162 h1 = __floats2bfloat162_rn(o4.z, o4.w);
            uint2 u;
            u.x = *(uint32_t*)&h0; u.y = *(uint32_t*)&h1;
            *(uint2*)(xb + q * 128 + lane * 4) = u;
        }
    } else {                                   // ---- label probe ----
        __shared__ int s_any;
        if (threadIdx.x == 0) s_any = 0;
        __syncthreads();
        if (lab[2 * threadIdx.x + 1] != 0) atomicOr(&s_any, 1);
        __syncthreads();
        if (threadIdx.x == 0) g_is64 = (s_any == 0) ? 1 : 0;
    }
}

// ---------------- bf16 mma.sync GEMM + fused exp/sum epilogue ---------------
// R12 data path; kc loop fully unrolled (ring offsets become constants),
// per-ks swizzle offsets hoisted, next-chunk cp.async issued after ks=0 so
// the tensor pipe starts immediately post-sync. 2 CTAs/SM.
#define SMEM_BYTES (NST * 32768)   // 98304: 3 stages x (A 16KB + B 16KB)

__global__ __launch_bounds__(256, 2) void k_gemm() {
    extern __shared__ char smem[];
    __shared__ float red[MBT];
    const uint32_t sA = smem_u32(smem);          // stage s: A at s*16384
    const uint32_t sB = sA + NST * 16384;        // stage s: B at s*16384

    const int tid  = threadIdx.x;
    const int lane = tid & 31;
    const int wid  = tid >> 5;
    const int wm   = wid >> 2;                   // 0..1
    const int wn   = wid & 3;                    // 0..3
    const int mBase = blockIdx.x * MBT;
    const int cBase = blockIdx.y * NBT;

    if (tid < MBT) red[tid] = 0.0f;              // ordered by first mainloop sync

    // ---- staging precompute: 1024 16B segs per operand per chunk ----
    const int srow = tid >> 3;                   // 0..31
    const int scol = tid & 7;
    const uint32_t st0 = (uint32_t)(srow * 128 + ((scol ^ (srow & 7)) << 4));
    const uint32_t st_a0 = sA + st0;
    const uint32_t st_b0 = sB + st0;
    const __nv_bfloat16* gp_a0 = g_xbf + (size_t)(mBase + srow) * DD + scol * 8;
    const __nv_bfloat16* gp_b[4];
    #pragma unroll
    for (int s = 0; s < 4; s++) {
        int br = cBase + srow + s * 32; if (br >= CC) br = CC - 1; // clamp; masked later
        gp_b[s] = g_wbf + (size_t)br * DD + scol * 8;
    }

    // ---- ldmatrix per-lane addressing (validated R8) ----
    const int arow = (lane & 7) + 8 * ((lane >> 3) & 1);
    const int akh  = lane >> 4;
    const int brow = (lane & 7) + 8 * (lane >> 4);
    const int bkh  = (lane >> 3) & 1;
    const int swz  = lane & 7;
    uint32_t aptr[4], bptr[2];
    #pragma unroll
    for (int mi = 0; mi < 4; mi++)
        aptr[mi] = sA + (uint32_t)((wm * 64 + mi * 16 + arow) * 128);
    #pragma unroll
    for (int jp = 0; jp < 2; jp++)
        bptr[jp] = sB + (uint32_t)((wn * 32 + jp * 16 + brow) * 128);

    // hoisted per-ks swizzle offsets (loop-invariant across kc)
    uint32_t cAo[4], cBo[4];
    #pragma unroll
    for (int ks = 0; ks < 4; ks++) {
        cAo[ks] = (uint32_t)(((ks * 2 + akh) ^ swz) << 4);
        cBo[ks] = (uint32_t)(((ks * 2 + bkh) ^ swz) << 4);
    }

    float d[4][4][4];
    #pragma unroll
    for (int mi = 0; mi < 4; mi++)
        #pragma unroll
        for (int nj = 0; nj < 4; nj++)
            #pragma unroll
            for (int r = 0; r < 4; r++) d[mi][nj][r] = 0.0f;

    // ---- prologue: stage chunks 0,1 into bufs 0,1 ----
    #pragma unroll
    for (int p = 0; p < 2; p++) {
        const uint32_t bo = (uint32_t)(p * 16384);
        #pragma unroll
        for (int s = 0; s < 4; s++) {
            CP_ASYNC16(st_a0 + bo + s * 4096, gp_a0 + s * 32 * DD + p * KC);
            CP_ASYNC16(st_b0 + bo + s * 4096, gp_b[s] + p * KC);
        }
        CP_COMMIT();
    }

    #pragma unroll
    for (int kc = 0; kc < NCH; kc++) {
        if (kc + 1 < NCH) CP_WAIT(1); else CP_WAIT(0);
        __syncthreads();                         // chunk kc landed; ring buf free

        const uint32_t bufoff = (uint32_t)((kc % NST) * 16384);

        // ---- ks = 0: start the tensor pipe immediately ----
        {
            uint32_t a[4][4], b[2][4];
            #pragma unroll
            for (int mi = 0; mi < 4; mi++) LDSM4(a[mi], aptr[mi] + bufoff + cAo[0]);
            #pragma unroll
            for (int jp = 0; jp < 2; jp++) LDSM4(b[jp], bptr[jp] + bufoff + cBo[0]);
            #pragma unroll
            for (int mi = 0; mi < 4; mi++) {
                MMA16816(d[mi][0], a[mi], b[0][0], b[0][1]);
                MMA16816(d[mi][1], a[mi], b[0][2], b[0][3]);
                MMA16816(d[mi][2], a[mi], b[1][0], b[1][1]);
                MMA16816(d[mi][3], a[mi], b[1][2], b[1][3]);
            }
        }

        // ---- issue next-chunk staging behind ks0's MMA stream ----
        if (kc + 2 < NCH) {
            const uint32_t nb = (uint32_t)(((kc + 2) % NST) * 16384);
            #pragma unroll
            for (int s = 0; s < 4; s++) {
                CP_ASYNC16(st_a0 + nb + s * 4096, gp_a0 + s * 32 * DD + (kc + 2) * KC);
                CP_ASYNC16(st_b0 + nb + s * 4096, gp_b[s] + (kc + 2) * KC);
            }
            CP_COMMIT();
        }

        // ---- ks = 1..3 ----
        #pragma unroll
        for (int ks = 1; ks < 4; ks++) {
            uint32_t a[4][4], b[2][4];
            #pragma unroll
            for (int mi = 0; mi < 4; mi++) LDSM4(a[mi], aptr[mi] + bufoff + cAo[ks]);
            #pragma unroll
            for (int jp = 0; jp < 2; jp++) LDSM4(b[jp], bptr[jp] + bufoff + cBo[ks]);
            #pragma unroll
            for (int mi = 0; mi < 4; mi++) {
                MMA16816(d[mi][0], a[mi], b[0][0], b[0][1]);
                MMA16816(d[mi][1], a[mi], b[0][2], b[0][3]);
                MMA16816(d[mi][2], a[mi], b[1][0], b[1][1]);
                MMA16816(d[mi][3], a[mi], b[1][2], b[1][3]);
            }
        }
    }

    // ---- epilogue: logits are d[] directly (scale folded into g_wbf) ----
    const int q  = lane & 3;
    const int g4 = lane >> 2;
    #pragma unroll
    for (int mi = 0; mi < 4; mi++) {
        float r0 = 0.0f, r1 = 0.0f;
        #pragma unroll
        for (int nj = 0; nj < 4; nj++) {
            int c0 = cBase + wn * 32 + nj * 8 + q * 2;
            if (c0 < CC)     { r0 += __expf(d[mi][nj][0] - SCALE);
                               r1 += __expf(d[mi][nj][2] - SCALE); }
            if (c0 + 1 < CC) { r0 += __expf(d[mi][nj][1] - SCALE);
                               r1 += __expf(d[mi][nj][3] - SCALE); }
        }
        r0 += __shfl_xor_sync(0xffffffffu, r0, 1);
        r0 += __shfl_xor_sync(0xffffffffu, r0, 2);
        r1 += __shfl_xor_sync(0xffffffffu, r1, 1);
        r1 += __shfl_xor_sync(0xffffffffu, r1, 2);
        if (q == 0) {
            atomicAdd(&red[wm * 64 + mi * 16 + g4],     r0);
            atomicAdd(&red[wm * 64 + mi * 16 + 8 + g4], r1);
        }
    }
    __syncthreads();
    if (tid < MBT) atomicAdd(&g_expsum[mBase + tid], red[tid]);
}

// ---------------- fused nll + final reduce (last-block pattern) -------------
__global__ void k_nll(const float* __restrict__ w, const void* __restrict__ labv,
                      float* __restrict__ out) {
    __shared__ bool s_last;
    __shared__ float sm[8];
    const int warp = threadIdx.x >> 5;
    const int lane = threadIdx.x & 31;
    const int i = blockIdx.x * 8 + warp;
    long long yi;
    if (g_is64) yi = ((const long long*)labv)[i];
    else        yi = (long long)((const int*)labv)[i];
    const float4* a4 = (const float4*)(g_xn + i * DD);
    const float4* w4 = (const float4*)(w + (size_t)yi * DD);
    float dot = 0.0f;
    #pragma unroll
    for (int qq = 0; qq < 4; qq++) {
        float4 a = a4[qq * 32 + lane];
        float4 b = w4[qq * 32 + lane];
        dot += a.x * b.x + a.y * b.y + a.z * b.z + a.w * b.w;
    }
    #pragma unroll
    for (int o = 16; o > 0; o >>= 1) dot += __shfl_xor_sync(0xffffffffu, dot, o);
    if (lane == 0) {
        g_nll[i] = SCALE + logf(g_expsum[i]) - g_wscale[yi] * dot;
        __threadfence();                         // publish before ticket
    }
    __syncthreads();
    if (threadIdx.x == 0) {
        int t = atomicAdd(&g_ctr, 1);
        s_last = (t == 63);                      // 64 blocks total
    }
    __syncthreads();
    if (s_last) {
        __threadfence();                         // acquire all g_nll writes
        float v = g_nll[threadIdx.x] + g_nll[threadIdx.x + 256];
        #pragma unroll
        for (int o = 16; o > 0; o >>= 1) v += __shfl_xor_sync(0xffffffffu, v, o);
        if (lane == 0) sm[warp] = v;
        __syncthreads();
        if (threadIdx.x < 8) {
            float u = sm[threadIdx.x];
            #pragma unroll
            for (int o = 4; o > 0; o >>= 1) u += __shfl_xor_sync(0x000000ffu, u, o);
            if (threadIdx.x == 0) {
                out[0] = u * (1.0f / (float)BB);
                g_ctr = 0;                       // reset for next replay
            }
        }
    }
}

// ---------------- launch -----------------------------------------------------
extern "C" void kernel_launch(void* const* d_in, const int* in_sizes, int n_in,
                              void* d_out, int out_size) {
    (void)out_size;
    const float* x = nullptr;
    const float* w = nullptr;
    const void* lab = nullptr;
    for (int i = 0; i < n_in; i++) {
        if (in_sizes[i] == BB * DD)      x = (const float*)d_in[i];
        else if (in_sizes[i] == CC * DD) w = (const float*)d_in[i];
        else if (in_sizes[i] == BB)      lab = d_in[i];
    }

    cudaFuncSetAttribute(k_gemm, cudaFuncAttributeMaxDynamicSharedMemorySize, SMEM_BYTES);

    k_prep<<<12565, 256>>>(x, w, (const int*)lab);
    dim3 g3(BB / MBT, (CC + NBT - 1) / NBT);   // (4, 782): batch-fast for L2 W reuse
    k_gemm<<<g3, 256, SMEM_BYTES>>>();
    k_nll<<<BB / 8, 256>>>(w, lab, (float*)d_out);
}

// round 17
// speedup vs baseline: 1.2552x; 1.0135x over previous
#include <cuda_runtime.h>
#include <cuda_bf16.h>
#include <math.h>
#include <stdint.h>

#define BB 512
#define DD 512
#define CC 100000
#define SCALE 64.0f

#define MBT 128          // batch tile
#define NBT 128          // class tile
#define KC  64           // K chunk (128 bytes bf16)
#define NCH (DD / KC)    // 8 chunks
#define NST 3            // cp.async pipeline stages

// k_prep block ranges
#define PB_W    12500    // W rows: blocks [0, 12500)
#define PB_X    12564    // x rows: blocks [12500, 12564)
#define PB_DOT  12628    // label-dot: blocks [12564, 12628)
#define PB_TOT  12628    // total blocks (probe folded into dot blocks)

// ---------------- device scratch ----------------
__device__ __nv_bfloat16  g_xbf[BB * DD];         // normalized x bf16
__device__ __nv_bfloat16  g_wbf[(size_t)CC * DD]; // W * (64/||w||) bf16
__device__ float          g_expsum[BB];           // per-row sum exp(L-64)
__device__ float          g_dotn[BB];             // 64*dot(x_i,w_yi)/(|x||w|)

// ---------------- PTX helpers (baseline compute_103-safe only) --------------
__device__ __forceinline__ uint32_t smem_u32(const void* p) {
    uint32_t a;
    asm("{ .reg .u64 t; cvta.to.shared.u64 t, %1; cvt.u32.u64 %0, t; }" : "=r"(a) : "l"(p));
    return a;
}
#define CP_ASYNC16(dst, src) \
    asm volatile("cp.async.cg.shared.global [%0], [%1], 16;" :: "r"(dst), "l"(src) : "memory")
#define CP_COMMIT() asm volatile("cp.async.commit_group;" ::: "memory")
#define CP_WAIT(n)  asm volatile("cp.async.wait_group %0;" :: "n"(n) : "memory")

#define LDSM4(r, addr) \
    asm volatile("ldmatrix.sync.aligned.m8n8.x4.shared.b16 {%0,%1,%2,%3}, [%4];" \
        : "=r"((r)[0]), "=r"((r)[1]), "=r"((r)[2]), "=r"((r)[3]) : "r"(addr))

#define MMA16816(d, a, b0v, b1v) \
    asm volatile("mma.sync.aligned.m16n8k16.row.col.f32.bf16.bf16.f32 " \
        "{%0,%1,%2,%3}, {%4,%5,%6,%7}, {%8,%9}, {%0,%1,%2,%3};" \
        : "+f"((d)[0]), "+f"((d)[1]), "+f"((d)[2]), "+f"((d)[3]) \
        : "r"((a)[0]), "r"((a)[1]), "r"((a)[2]), "r"((a)[3]), "r"(b0v), "r"(b1v))

// ---------------- fused prep: W norm+convert | x norm | label-dot -----------
__global__ void k_prep(const float* __restrict__ x, const float* __restrict__ w,
                       const int* __restrict__ lab) {
    const int bid = blockIdx.x;
    const int warp = threadIdx.x >> 5;
    const int lane = threadIdx.x & 31;

    if (bid < PB_W) {                          // ---- W path ----
        const int c = bid * 8 + warp;
        const float4* w4 = (const float4*)(w + (size_t)c * DD);
        float4 v[4];
        float ss = 0.0f;
        #pragma unroll
        for (int q = 0; q < 4; q++) {
            v[q] = w4[q * 32 + lane];
            ss += v[q].x * v[q].x + v[q].y * v[q].y + v[q].z * v[q].z + v[q].w * v[q].w;
        }
        #pragma unroll
        for (int o = 16; o > 0; o >>= 1) ss += __shfl_xor_sync(0xffffffffu, ss, o);
        const float sc = SCALE / fmaxf(sqrtf(ss), 1e-12f);
        __nv_bfloat16* dst = g_wbf + (size_t)c * DD;
        #pragma unroll
        for (int q = 0; q < 4; q++) {
            __nv_bfloat162 h0 = __floats2bfloat162_rn(v[q].x * sc, v[q].y * sc);
            __nv_bfloat162 h1 = __floats2bfloat162_rn(v[q].z * sc, v[q].w * sc);
            uint2 u;
            u.x = *(uint32_t*)&h0; u.y = *(uint32_t*)&h1;
            *(uint2*)(dst + q * 128 + lane * 4) = u;
        }
    } else if (bid < PB_X) {                   // ---- x path ----
        const int m = (bid - PB_W) * 8 + warp;
        const float4* x4 = (const float4*)(x + (size_t)m * DD);
        float4 v[4];
        float ss = 0.0f;
        #pragma unroll
        for (int q = 0; q < 4; q++) {
            v[q] = x4[q * 32 + lane];
            ss += v[q].x * v[q].x + v[q].y * v[q].y + v[q].z * v[q].z + v[q].w * v[q].w;
        }
        #pragma unroll
        for (int o = 16; o > 0; o >>= 1) ss += __shfl_xor_sync(0xffffffffu, ss, o);
        const float inv = 1.0f / fmaxf(sqrtf(ss), 1e-12f);
        if (lane == 0) g_expsum[m] = 0.0f;     // re-zeroed every graph replay
        __nv_bfloat16* xb = g_xbf + (size_t)m * DD;
        #pragma unroll
        for (int q = 0; q < 4; q++) {
            __nv_bfloat162 h0 = __floats2bfloat162_rn(v[q].x * inv, v[q].y * inv);
            __nv_bfloat162 h1 = __floats2bfloat162_rn(v[q].z * inv, v[q].w * inv);
            uint2 u;
            u.x = *(uint32_t*)&h0; u.y = *(uint32_t*)&h1;
            *(uint2*)(xb + q * 128 + lane * 4) = u;
        }
    } else {                                   // ---- label-dot path ----
        // Per-block local label-dtype probe (blocks are unordered).
        __shared__ int s_any;
        if (threadIdx.x == 0) s_any = 0;
        __syncthreads();
        if (lab[2 * threadIdx.x + 1] != 0) atomicOr(&s_any, 1);
        __syncthreads();
        const bool is64 = (s_any == 0);

        const int i = (bid - PB_X) * 8 + warp;  // batch row 0..511
        long long yi;
        if (is64) yi = ((const long long*)lab)[i];
        else      yi = (long long)lab[i];
        const float4* a4 = (const float4*)(x + (size_t)i * DD);
        const float4* w4 = (const float4*)(w + (size_t)yi * DD);
        float sx = 0.0f, sw = 0.0f, sd = 0.0f;
        #pragma unroll
        for (int q = 0; q < 4; q++) {
            float4 a = a4[q * 32 + lane];
            float4 b = w4[q * 32 + lane];
            sx += a.x * a.x + a.y * a.y + a.z * a.z + a.w * a.w;
            sw += b.x * b.x + b.y * b.y + b.z * b.z + b.w * b.w;
            sd += a.x * b.x + a.y * b.y + a.z * b.z + a.w * b.w;
        }
        #pragma unroll
        for (int o = 16; o > 0; o >>= 1) {
            sx += __shfl_xor_sync(0xffffffffu, sx, o);
            sw += __shfl_xor_sync(0xffffffffu, sw, o);
            sd += __shfl_xor_sync(0xffffffffu, sd, o);
        }
        if (lane == 0)
            g_dotn[i] = SCALE * sd /
                        (fmaxf(sqrtf(sx), 1e-12f) * fmaxf(sqrtf(sw), 1e-12f));
    }
}

// ---------------- bf16 mma.sync GEMM + fused exp/sum epilogue ---------------
// R16 config verbatim (best measured ~111us): unrolled kc ring, hoisted
// swizzle offsets, cp.async issued behind ks0, 2 CTAs/SM.
#define SMEM_BYTES (NST * 32768)   // 98304: 3 stages x (A 16KB + B 16KB)

__global__ __launch_bounds__(256, 2) void k_gemm() {
    extern __shared__ char smem[];
    __shared__ float red[MBT];
    const uint32_t sA = smem_u32(smem);          // stage s: A at s*16384
    const uint32_t sB = sA + NST * 16384;        // stage s: B at s*16384

    const int tid  = threadIdx.x;
    const int lane = tid & 31;
    const int wid  = tid >> 5;
    const int wm   = wid >> 2;                   // 0..1
    const int wn   = wid & 3;                    // 0..3
    const int mBase = blockIdx.x * MBT;
    const int cBase = blockIdx.y * NBT;

    if (tid < MBT) red[tid] = 0.0f;              // ordered by first mainloop sync

    // ---- staging precompute: 1024 16B segs per operand per chunk ----
    const int srow = tid >> 3;                   // 0..31
    const int scol = tid & 7;
    const uint32_t st0 = (uint32_t)(srow * 128 + ((scol ^ (srow & 7)) << 4));
    const uint32_t st_a0 = sA + st0;
    const uint32_t st_b0 = sB + st0;
    const __nv_bfloat16* gp_a0 = g_xbf + (size_t)(mBase + srow) * DD + scol * 8;
    const __nv_bfloat16* gp_b[4];
    #pragma unroll
    for (int s = 0; s < 4; s++) {
        int br = cBase + srow + s * 32; if (br >= CC) br = CC - 1; // clamp; masked later
        gp_b[s] = g_wbf + (size_t)br * DD + scol * 8;
    }

    // ---- ldmatrix per-lane addressing (validated R8) ----
    const int arow = (lane & 7) + 8 * ((lane >> 3) & 1);
    const int akh  = lane >> 4;
    const int brow = (lane & 7) + 8 * (lane >> 4);
    const int bkh  = (lane >> 3) & 1;
    const int swz  = lane & 7;
    uint32_t aptr[4], bptr[2];
    #pragma unroll
    for (int mi = 0; mi < 4; mi++)
        aptr[mi] = sA + (uint32_t)((wm * 64 + mi * 16 + arow) * 128);
    #pragma unroll
    for (int jp = 0; jp < 2; jp++)
        bptr[jp] = sB + (uint32_t)((wn * 32 + jp * 16 + brow) * 128);

    // hoisted per-ks swizzle offsets (loop-invariant across kc)
    uint32_t cAo[4], cBo[4];
    #pragma unroll
    for (int ks = 0; ks < 4; ks++) {
        cAo[ks] = (uint32_t)(((ks * 2 + akh) ^ swz) << 4);
        cBo[ks] = (uint32_t)(((ks * 2 + bkh) ^ swz) << 4);
    }

    float d[4][4][4];
    #pragma unroll
    for (int mi = 0; mi < 4; mi++)
        #pragma unroll
        for (int nj = 0; nj < 4; nj++)
            #pragma unroll
            for (int r = 0; r < 4; r++) d[mi][nj][r] = 0.0f;

    // ---- prologue: stage chunks 0,1 into bufs 0,1 ----
    #pragma unroll
    for (int p = 0; p < 2; p++) {
        const uint32_t bo = (uint32_t)(p * 16384);
        #pragma unroll
        for (int s = 0; s < 4; s++) {
            CP_ASYNC16(st_a0 + bo + s * 4096, gp_a0 + s * 32 * DD + p * KC);
            CP_ASYNC16(st_b0 + bo + s * 4096, gp_b[s] + p * KC);
        }
        CP_COMMIT();
    }

    #pragma unroll
    for (int kc = 0; kc < NCH; kc++) {
        if (kc + 1 < NCH) CP_WAIT(1); else CP_WAIT(0);
        __syncthreads();                         // chunk kc landed; ring buf free

        const uint32_t bufoff = (uint32_t)((kc % NST) * 16384);

        // ---- ks = 0: start the tensor pipe immediately ----
        {
            uint32_t a[4][4], b[2][4];
            #pragma unroll
            for (int mi = 0; mi < 4; mi++) LDSM4(a[mi], aptr[mi] + bufoff + cAo[0]);
            #pragma unroll
            for (int jp = 0; jp < 2; jp++) LDSM4(b[jp], bptr[jp] + bufoff + cBo[0]);
            #pragma unroll
            for (int mi = 0; mi < 4; mi++) {
                MMA16816(d[mi][0], a[mi], b[0][0], b[0][1]);
                MMA16816(d[mi][1], a[mi], b[0][2], b[0][3]);
                MMA16816(d[mi][2], a[mi], b[1][0], b[1][1]);
                MMA16816(d[mi][3], a[mi], b[1][2], b[1][3]);
            }
        }

        // ---- issue next-chunk staging behind ks0's MMA stream ----
        if (kc + 2 < NCH) {
            const uint32_t nb = (uint32_t)(((kc + 2) % NST) * 16384);
            #pragma unroll
            for (int s = 0; s < 4; s++) {
                CP_ASYNC16(st_a0 + nb + s * 4096, gp_a0 + s * 32 * DD + (kc + 2) * KC);
                CP_ASYNC16(st_b0 + nb + s * 4096, gp_b[s] + (kc + 2) * KC);
            }
            CP_COMMIT();
        }

        // ---- ks = 1..3 ----
        #pragma unroll
        for (int ks = 1; ks < 4; ks++) {
            uint32_t a[4][4], b[2][4];
            #pragma unroll
            for (int mi = 0; mi < 4; mi++) LDSM4(a[mi], aptr[mi] + bufoff + cAo[ks]);
            #pragma unroll
            for (int jp = 0; jp < 2; jp++) LDSM4(b[jp], bptr[jp] + bufoff + cBo[ks]);
            #pragma unroll
            for (int mi = 0; mi < 4; mi++) {
                MMA16816(d[mi][0], a[mi], b[0][0], b[0][1]);
                MMA16816(d[mi][1], a[mi], b[0][2], b[0][3]);
                MMA16816(d[mi][2], a[mi], b[1][0], b[1][1]);
                MMA16816(d[mi][3], a[mi], b[1][2], b[1][3]);
            }
        }
    }

    // ---- epilogue: logits are d[] directly (scale folded into g_wbf) ----
    const int q  = lane & 3;
    const int g4 = lane >> 2;
    #pragma unroll
    for (int mi = 0; mi < 4; mi++) {
        float r0 = 0.0f, r1 = 0.0f;
        #pragma unroll
        for (int nj = 0; nj < 4; nj++) {
            int c0 = cBase + wn * 32 + nj * 8 + q * 2;
            if (c0 < CC)     { r0 += __expf(d[mi][nj][0] - SCALE);
                               r1 += __expf(d[mi][nj][2] - SCALE); }
            if (c0 + 1 < CC) { r0 += __expf(d[mi][nj][1] - SCALE);
                               r1 += __expf(d[mi][nj][3] - SCALE); }
        }
        r0 += __shfl_xor_sync(0xffffffffu, r0, 1);
        r0 += __shfl_xor_sync(0xffffffffu, r0, 2);
        r1 += __shfl_xor_sync(0xffffffffu, r1, 1);
        r1 += __shfl_xor_sync(0xffffffffu, r1, 2);
        if (q == 0) {
            atomicAdd(&red[wm * 64 + mi * 16 + g4],     r0);
            atomicAdd(&red[wm * 64 + mi * 16 + 8 + g4], r1);
        }
    }
    __syncthreads();
    if (tid < MBT) atomicAdd(&g_expsum[mBase + tid], red[tid]);
}

// ---------------- final: nll from precomputed dot + deterministic reduce ----
__global__ void k_final(float* __restrict__ out) {
    __shared__ float sm[16];
    const int t = threadIdx.x;                 // 512 threads
    float v = SCALE + logf(g_expsum[t]) - g_dotn[t];
    #pragma unroll
    for (int o = 16; o > 0; o >>= 1) v += __shfl_xor_sync(0xffffffffu, v, o);
    if ((t & 31) == 0) sm[t >> 5] = v;
    __syncthreads();
    if (t < 16) {
        float u = sm[t];
        #pragma unroll
        for (int o = 8; o > 0; o >>= 1) u += __shfl_xor_sync(0x0000ffffu, u, o);
        if (t == 0) out[0] = u * (1.0f / (float)BB);
    }
}

// ---------------- launch -----------------------------------------------------
extern "C" void kernel_launch(void* const* d_in, const int* in_sizes, int n_in,
                              void* d_out, int out_size) {
    (void)out_size;
    const float* x = nullptr;
    const float* w = nullptr;
    const void* lab = nullptr;
    for (int i = 0; i < n_in; i++) {
        if (in_sizes[i] == BB * DD)      x = (const float*)d_in[i];
        else if (in_sizes[i] == CC * DD) w = (const float*)d_in[i];
        else if (in_sizes[i] == BB)      lab = d_in[i];
    }

    cudaFuncSetAttribute(k_gemm, cudaFuncAttributeMaxDynamicSharedMemorySize, SMEM_BYTES);

    k_prep<<<PB_TOT, 256>>>(x, w, (const int*)lab);
    dim3 g3(BB / MBT, (CC + NBT - 1) / NBT);   // (4, 782): batch-fast for L2 W reuse
    k_gemm<<<g3, 256, SMEM_BYTES>>>();
    k_final<<<1, BB>>>((float*)d_out);
}